// round 14
// baseline (speedup 1.0000x reference)
#include <cuda_runtime.h>
#include <cstdint>
#include <cfloat>
#include <math.h>

#define D_MODEL 4096
#define VOCAB   32000
#define TK      10
#define DEPTH   5
#define TT      59
#define VSPLIT  8
#define KFC     (2*D_MODEL)

#define KTILE   4
#define NBUF    4
#define SMEM_W  (NBUF*KTILE*512*4)     // 32768 B
#define SMEM_H  (NBUF*KTILE*12*8)      // 1536 B
#define SMEM_TOT (SMEM_W + SMEM_H)     // 34304 B < 48KB default

#define HSNUM   14       // head split: 63 x 14 = 882 CTAs (one wave @6/SM)
#define FSNUM   110      // fc split:    8 x 110 = 880 CTAs
#define T_HEAD  (D_MODEL / KTILE)      // 1024 k-tiles
#define T_FC    (KFC / KTILE)          // 2048 k-tiles

typedef unsigned long long ull;

// ---------------- device scratch ----------------
__device__ __align__(16) float g_part[4718592];   // split-K partials
__device__ float  g_outh[TK][D_MODEL];            // fc output (tanh)
__device__ ull    g_hdupA[TK * D_MODEL];          // dup'd h for head gemm
__device__ ull    g_hdupB[TK * KFC];              // dup'd h for fc gemm
__device__ float  g_scores_flat[512];
__device__ int    g_ss_flat[512];
__device__ int    g_parents_flat[64];
__device__ float  g_scores[TK];
__device__ int    g_input_ids[TK];
__device__ int    g_out_ids[TK];
__device__ int    g_cs_index[TK];
__device__ float  g_topk_p[TK][TK];
__device__ int    g_topk_i[TK][TK];
__device__ float  g_cand_v[TK][VSPLIT][TK];
__device__ int    g_cand_i[TK][VSPLIT][TK];
__device__ float  g_lse_m[TK][VSPLIT];
__device__ float  g_lse_s[TK][VSPLIT];

// ---------------- helpers ----------------
__device__ __forceinline__ void ffma2(ull &acc, ull a, ull b) {
    asm("fma.rn.f32x2 %0, %1, %2, %0;" : "+l"(acc) : "l"(a), "l"(b));
}

__device__ __forceinline__ ull dupf(float v) {
    unsigned u = __float_as_uint(v);
    return (ull)u | ((ull)u << 32);
}

__device__ __forceinline__ bool betterf(float av, int ai, float bv, int bi) {
    return (av > bv) || (av == bv && ai < bi);
}

__device__ __forceinline__ void cpa16(uint32_t s, const void* g) {
    asm volatile("cp.async.cg.shared.global [%0], [%1], 16;" :: "r"(s), "l"(g) : "memory");
}
__device__ __forceinline__ void cpa8(uint32_t s, const void* g) {
    asm volatile("cp.async.ca.shared.global [%0], [%1], 8;" :: "r"(s), "l"(g) : "memory");
}
#define CP_COMMIT() asm volatile("cp.async.commit_group;" ::: "memory")
#define CP_WAIT()   asm volatile("cp.async.wait_group %0;" :: "n"(NBUF - 1) : "memory")

// ---------------- cp.async multistage split-K GEMV-batch ----------------
// 128 threads; thread owns 4 columns. 512 cols/block. W staged via cp.async
// into NBUF x (KTILE x 512 f32) smem buffers (wait_group keeps NBUF-1 tiles in
// flight); h (pre-dup'd ull, [r][k]) staged into [kk][r] (12-ull padded rows).
// HD: 0 = g_hdupA (K=D_MODEL), 1 = g_hdupB (K=KFC). Chosen IN-KERNEL.
template<int ROWS, int HD>
__global__ __launch_bounds__(128)
void pipe_gemm(const float* __restrict__ W, int K, int N, int T, int S)
{
    extern __shared__ char smem[];
    const ull* hdup = (HD == 0) ? g_hdupA : g_hdupB;
    const int tid  = threadIdx.x;
    const int colb = blockIdx.x * 512;
    const int col  = colb + tid * 4;
    const bool vC  = col < N;               // N multiple of 4
    const int ts   = (blockIdx.y * T) / S;
    const int te   = ((blockIdx.y + 1) * T) / S;

    const uint32_t wbase = (uint32_t)__cvta_generic_to_shared(smem);
    const uint32_t hbase = wbase + SMEM_W;

    ull acc0[ROWS], acc1[ROWS];
    #pragma unroll
    for (int r = 0; r < ROWS; r++) { acc0[r] = 0; acc1[r] = 0; }

    auto stage = [&](int kt, int b) {
        const float* ws = W + (size_t)kt * KTILE * N;
        const uint32_t wd = wbase + (uint32_t)b * (KTILE * 512 * 4);
        int gc = colb + tid * 4;
        gc = (gc <= N - 4) ? gc : (N - 4);
        #pragma unroll
        for (int u = 0; u < KTILE; u++)
            cpa16(wd + (uint32_t)(u * 2048 + tid * 16), ws + (size_t)u * N + gc);
        if (tid < ROWS * KTILE) {
            int r  = tid / KTILE;
            int kk = tid - r * KTILE;
            cpa8(hbase + (uint32_t)b * (KTILE * 12 * 8) + (uint32_t)(kk * 96 + r * 8),
                 hdup + (size_t)r * K + (size_t)kt * KTILE + kk);
        }
    };

    #pragma unroll
    for (int s = 0; s < NBUF; s++) {
        if (ts + s < te) stage(ts + s, s);
        CP_COMMIT();
    }

    for (int i = ts; i < te; i++) {
        CP_WAIT();
        __syncthreads();
        const int b = (i - ts) & (NBUF - 1);
        const char* wrow = smem + (size_t)b * (KTILE * 512 * 4) + tid * 16;
        const char* hrow = smem + SMEM_W + (size_t)b * (KTILE * 12 * 8);
        #pragma unroll
        for (int kk = 0; kk < KTILE; kk++) {
            float4 wv = *reinterpret_cast<const float4*>(wrow + kk * 2048);
            ulonglong2 wp = *reinterpret_cast<ulonglong2*>(&wv);
            #pragma unroll
            for (int rp = 0; rp < ROWS / 2; rp++) {
                ulonglong2 h = *reinterpret_cast<const ulonglong2*>(hrow + kk * 96 + rp * 16);
                ffma2(acc0[2*rp],   wp.x, h.x);
                ffma2(acc1[2*rp],   wp.y, h.x);
                ffma2(acc0[2*rp+1], wp.x, h.y);
                ffma2(acc1[2*rp+1], wp.y, h.y);
            }
            if (ROWS & 1) {
                ull h = *reinterpret_cast<const ull*>(hrow + kk * 96 + (ROWS - 1) * 8);
                ffma2(acc0[ROWS-1], wp.x, h);
                ffma2(acc1[ROWS-1], wp.y, h);
            }
        }
        __syncthreads();
        if (i + NBUF < te) stage(i + NBUF, (i - ts) & (NBUF - 1));
        CP_COMMIT();
    }

    if (vC) {
        float* dst = g_part + (size_t)blockIdx.y * ROWS * N + col;
        #pragma unroll
        for (int r = 0; r < ROWS; r++) {
            ulonglong2 o; o.x = acc0[r]; o.y = acc1[r];
            *reinterpret_cast<ulonglong2*>(dst + (size_t)r * N) = o;
        }
    }
}

// ---------------- per-slice partial-reduce + streaming LSE + top-10 ----------------
template<int NS>
__global__ __launch_bounds__(512)
void head_topk_part(int rows)
{
    __shared__ float sval[512 * 10];
    __shared__ int   sidx[512 * 10];
    __shared__ float sm[512];
    __shared__ float ssm[512];
    const int r   = blockIdx.x;
    const int s   = blockIdx.y;
    const int tid = threadIdx.x;
    const int q0  = s * (VOCAB / VSPLIT / 4);
    const int q1  = q0 + (VOCAB / VSPLIT / 4);

    float bv[10]; int bi[10];
    #pragma unroll
    for (int j = 0; j < 10; j++) { bv[j] = -FLT_MAX; bi[j] = 0x7fffffff; }
    float runm = -FLT_MAX, runs = 0.f;

    const float4* pp = reinterpret_cast<const float4*>(g_part);
    for (int q = q0 + tid; q < q1; q += 512) {
        float4 a = pp[((size_t)0 * rows + r) * (VOCAB / 4) + q];
        #pragma unroll 7
        for (int p = 1; p < NS; p++) {
            float4 t = pp[((size_t)p * rows + r) * (VOCAB / 4) + q];
            a.x += t.x; a.y += t.y; a.z += t.z; a.w += t.w;
        }
        int vbase = q * 4;
        float xs[4] = {a.x, a.y, a.z, a.w};
        #pragma unroll
        for (int e = 0; e < 4; e++) {
            float x = xs[e];
            int   v = vbase + e;
            float nm = fmaxf(runm, x);
            runs = runs * __expf(runm - nm) + __expf(x - nm);
            runm = nm;
            if (betterf(x, v, bv[9], bi[9])) {
                bv[9] = x; bi[9] = v;
                #pragma unroll
                for (int j = 9; j > 0; j--) {
                    if (betterf(bv[j], bi[j], bv[j-1], bi[j-1])) {
                        float tv = bv[j]; bv[j] = bv[j-1]; bv[j-1] = tv;
                        int   ti = bi[j]; bi[j] = bi[j-1]; bi[j-1] = ti;
                    }
                }
            }
        }
    }
    #pragma unroll
    for (int j = 0; j < 10; j++) { sval[tid*10+j] = bv[j]; sidx[tid*10+j] = bi[j]; }
    sm[tid] = runm; ssm[tid] = runs;
    __syncthreads();

    for (int n = 256; n >= 1; n >>= 1) {
        if (tid < n) {
            const float* pa = &sval[tid * 10];
            const int*   qa = &sidx[tid * 10];
            const float* pb = &sval[(tid + n) * 10];
            const int*   qb = &sidx[(tid + n) * 10];
            float ov[10]; int oi[10];
            int ia = 0, ib = 0;
            #pragma unroll
            for (int j = 0; j < 10; j++) {
                bool ta = betterf(pa[ia], qa[ia], pb[ib], qb[ib]);
                ov[j] = ta ? pa[ia] : pb[ib];
                oi[j] = ta ? qa[ia] : qb[ib];
                if (ta) ia++; else ib++;
            }
            #pragma unroll
            for (int j = 0; j < 10; j++) { sval[tid*10+j] = ov[j]; sidx[tid*10+j] = oi[j]; }
            float m1 = sm[tid], m2 = sm[tid + n];
            float mm = fmaxf(m1, m2);
            ssm[tid] = ssm[tid] * __expf(m1 - mm) + ssm[tid + n] * __expf(m2 - mm);
            sm[tid] = mm;
        }
        __syncthreads();
    }
    if (tid < 10) {
        g_cand_v[r][s][tid] = sval[tid];
        g_cand_i[r][s][tid] = sidx[tid];
        if (tid == 0) { g_lse_m[r][s] = sm[0]; g_lse_s[r][s] = ssm[0]; }
    }
}

// ---------------- smem-cached merge ----------------
// scv/sci: [rows][VSPLIT][TK] candidate copies; slm/sls: [rows][VSPLIT] LSE pieces.
__device__ __forceinline__ void merge_from_smem(
    int r, const float (*scv)[VSPLIT][TK], const int (*sci)[VSPLIT][TK],
    const float (*slm)[VSPLIT], const float (*sls)[VSPLIT])
{
    float mt = -FLT_MAX;
    #pragma unroll
    for (int s = 0; s < VSPLIT; s++) mt = fmaxf(mt, slm[r][s]);
    float st = 0.f;
    #pragma unroll
    for (int s = 0; s < VSPLIT; s++) st += sls[r][s] * __expf(slm[r][s] - mt);
    float lse = logf(st) + mt;

    int ptr[VSPLIT];
    #pragma unroll
    for (int s = 0; s < VSPLIT; s++) ptr[s] = 0;
    #pragma unroll
    for (int j = 0; j < TK; j++) {
        float bvv = -FLT_MAX; int bii = 0x7fffffff; int bs = 0;
        #pragma unroll
        for (int s = 0; s < VSPLIT; s++) {
            float cv = scv[r][s][ptr[s]];
            int   ci = sci[r][s][ptr[s]];
            if (betterf(cv, ci, bvv, bii)) { bvv = cv; bii = ci; bs = s; }
        }
        ptr[bs]++;
        g_topk_p[r][j] = bvv - lse;
        g_topk_i[r][j] = bii;
    }
}

__global__ __launch_bounds__(128)
void init_merge_kernel()
{
    __shared__ float scv[1][VSPLIT][TK];
    __shared__ int   sci[1][VSPLIT][TK];
    __shared__ float slm[1][VSPLIT];
    __shared__ float sls[1][VSPLIT];
    int tid = threadIdx.x;
    if (tid < VSPLIT * TK) {
        (&scv[0][0][0])[tid] = (&g_cand_v[0][0][0])[tid];
        (&sci[0][0][0])[tid] = (&g_cand_i[0][0][0])[tid];
    }
    if (tid < VSPLIT) { slm[0][tid] = g_lse_m[0][tid]; sls[0][tid] = g_lse_s[0][tid]; }
    __syncthreads();
    if (tid == 0) {
        merge_from_smem(0, scv, sci, slm, sls);
        #pragma unroll
        for (int j = 0; j < TK; j++) {
            float lp = g_topk_p[0][j];
            int   ix = g_topk_i[0][j];
            g_scores[j]      = lp;
            g_scores_flat[j] = lp;
            g_ss_flat[j]     = ix;
            g_input_ids[j]   = ix;
            g_cs_index[j]    = j;
        }
        g_parents_flat[0] = 0;
    }
}

// ---------------- fused merge + level bookkeeping ----------------
__global__ __launch_bounds__(128)
void level_kernel(int level)
{
    __shared__ float scv[TK][VSPLIT][TK];
    __shared__ int   sci[TK][VSPLIT][TK];
    __shared__ float slm[TK][VSPLIT];
    __shared__ float sls[TK][VSPLIT];
    __shared__ float cu[128];
    __shared__ float rv[128];
    __shared__ int   ri[128];
    int tid = threadIdx.x;

    for (int x = tid; x < TK * VSPLIT * TK; x += 128) {
        (&scv[0][0][0])[x] = (&g_cand_v[0][0][0])[x];
        (&sci[0][0][0])[x] = (&g_cand_i[0][0][0])[x];
    }
    if (tid < TK * VSPLIT) {
        (&slm[0][0])[tid] = (&g_lse_m[0][0])[tid];
        (&sls[0][0])[tid] = (&g_lse_s[0][0])[tid];
    }
    if (tid < TK) {
        int bias1 = (level > 0) ? TK : 0;
        int bias2 = (level > 1) ? (level - 1) : 0;
        int bias  = 1 + TK * TK * bias2 + bias1;
        g_parents_flat[1 + TK * level + tid] = g_cs_index[tid] + bias;
    }
    __syncthreads();
    if (tid < TK) merge_from_smem(tid, scv, sci, slm, sls);
    __syncthreads();
    float v = -FLT_MAX;
    if (tid < 100) {
        int r = tid / 10, c = tid - r * 10;
        v = g_topk_p[r][c] + g_scores[r];
        g_scores_flat[10 + 100 * level + tid] = v;
        g_ss_flat[10 + 100 * level + tid]     = g_topk_i[r][c];
    }
    cu[tid] = v;
    __syncthreads();
    for (int j = 0; j < TK; j++) {
        rv[tid] = cu[tid]; ri[tid] = tid;
        __syncthreads();
        #pragma unroll
        for (int n = 64; n >= 1; n >>= 1) {
            if (tid < n) {
                if (betterf(rv[tid + n], ri[tid + n], rv[tid], ri[tid])) {
                    rv[tid] = rv[tid + n]; ri[tid] = ri[tid + n];
                }
            }
            __syncthreads();
        }
        if (tid == 0) {
            int bx = ri[0];
            g_cs_index[j]  = bx;
            g_scores[j]    = rv[0];
            g_out_ids[j]   = bx / 10;
            g_input_ids[j] = g_topk_i[bx / 10][bx % 10];
            cu[bx] = -FLT_MAX;
        }
        __syncthreads();
    }
}

// ---------------- prep kernels (write duplicated h arrays) ----------------
__global__ void hdup_init_kernel(const float* __restrict__ lh)
{
    int j = blockIdx.x * 256 + threadIdx.x;
    if (j < D_MODEL) g_hdupA[j] = dupf(lh[j]);
}

__global__ __launch_bounds__(256)
void prep_fc_dup_kernel(const float* __restrict__ E, const float* __restrict__ lh, int level)
{
    #pragma unroll
    for (int e = 0; e < 4; e++) {
        int x = blockIdx.x * 1024 + e * 256 + threadIdx.x;   // 80 blocks -> TK*KFC
        int r = x / KFC, k = x - r * KFC;
        float v;
        if (k < D_MODEL)        v = E[(size_t)g_input_ids[r] * D_MODEL + k];
        else if (level == 0)    v = lh[k - D_MODEL];
        else                    v = g_outh[g_out_ids[r]][k - D_MODEL];
        g_hdupB[(size_t)r * KFC + k] = dupf(v);
    }
}

// ---------------- fc reduce: sum FSNUM partials, tanh, write outh + hdupA ----------------
__global__ __launch_bounds__(128)
void fc_reduce_kernel()
{
    int q = blockIdx.x * 128 + threadIdx.x;     // 160 blocks * 128 = 20480 float2s
    const float2* pp = reinterpret_cast<const float2*>(g_part);
    float ax = 0.f, ay = 0.f;
    #pragma unroll 10
    for (int p = 0; p < FSNUM; p++) {
        float2 t = pp[(size_t)p * (TK * D_MODEL / 2) + q];
        ax += t.x; ay += t.y;
    }
    float t0 = tanhf(ax), t1 = tanhf(ay);
    reinterpret_cast<float2*>(&g_outh[0][0])[q] = make_float2(t0, t1);
    int r = q / (D_MODEL / 2);
    int c = (q - r * (D_MODEL / 2)) * 2;
    g_hdupA[(size_t)r * D_MODEL + c]     = dupf(t0);
    g_hdupA[(size_t)r * D_MODEL + c + 1] = dupf(t1);
}

// ---------------- final tree assembly ----------------
__global__ __launch_bounds__(256)
void final_kernel(const int* __restrict__ sample_token, float* __restrict__ out)
{
    __shared__ float sv[512];
    __shared__ float rv[256];
    __shared__ int   ri[256];
    __shared__ int   tsi_u[TT];
    __shared__ int   tsi[TT];
    __shared__ int   pp[TT + 1];
    __shared__ unsigned char noleaf[TT + 1];
    __shared__ unsigned char m[TT + 1][TT + 1];
    __shared__ int   poss[TT + 1];
    const int tid = threadIdx.x;

    for (int j = tid; j < 512; j += 256)
        sv[j] = (j < 510) ? g_scores_flat[j] : -FLT_MAX;
    __syncthreads();

    for (int round = 0; round < TT; round++) {
        float a = sv[tid], b = sv[tid + 256];
        float mv; int mi;
        if (betterf(a, tid, b, tid + 256)) { mv = a; mi = tid; } else { mv = b; mi = tid + 256; }
        rv[tid] = mv; ri[tid] = mi;
        __syncthreads();
        for (int n = 128; n >= 1; n >>= 1) {
            if (tid < n) {
                if (betterf(rv[tid + n], ri[tid + n], rv[tid], ri[tid])) {
                    rv[tid] = rv[tid + n]; ri[tid] = ri[tid + n];
                }
            }
            __syncthreads();
        }
        if (tid == 0) { tsi_u[round] = ri[0]; sv[ri[0]] = -FLT_MAX; }
        __syncthreads();
    }

    if (tid < TT) {
        int v = tsi_u[tid];
        int rank = 0;
        for (int j = 0; j < TT; j++) rank += (tsi_u[j] < v);
        tsi[rank] = v;
    }
    __syncthreads();

    if (tid < TT) {
        int t  = tsi[tid];
        int dp = g_parents_flat[t / TK];
        int tgt = dp - 1;
        int lb = 0;
        for (int j = 0; j < TT; j++) lb += (tsi[j] < tgt);
        int mi = ((dp == 0) ? -1 : lb) + 1;
        pp[tid + 1] = mi;
    }
    if (tid == 0) pp[0] = 0;
    if (tid <= TT) noleaf[tid] = 0;
    for (int j = tid; j < (TT + 1) * (TT + 1); j += 256)
        (&m[0][0])[j] = 0;
    __syncthreads();
    if (tid < TT) noleaf[pp[tid + 1]] = 1;
    __syncthreads();

    int a[DEPTH + 2];
    int pos = 0;
    if (tid <= TT) {
        a[0] = tid;
        #pragma unroll
        for (int jj = 1; jj < DEPTH + 2; jj++) a[jj] = pp[a[jj - 1]];
        #pragma unroll
        for (int jj = 0; jj < DEPTH + 2; jj++) m[tid][a[jj]] = 1;
        m[tid][0] = 1;
    }
    __syncthreads();
    if (tid <= TT) {
        int s = 0;
        for (int c = 0; c <= TT; c++) s += m[tid][c];
        pos = s - 1;
        poss[tid] = pos;
    }
    __syncthreads();

    if (tid == 0) out[0] = (float)sample_token[0];
    if (tid < TT) out[1 + tid] = (float)g_ss_flat[tsi[tid]];
    if (tid <= TT) {
        #pragma unroll
        for (int c = 0; c < DEPTH + 2; c++) {
            int kk  = pos - c;
            int idx = kk < 0 ? 0 : (kk > DEPTH + 1 ? DEPTH + 1 : kk);
            int ch  = (kk >= 0) ? a[idx] : -1;
            if (noleaf[tid]) ch = -1;
            out[60 + tid * (DEPTH + 2) + c] = (float)ch;
        }
        out[60 + (TT + 1) * (DEPTH + 2) + (TT + 1) * (TT + 1) + tid] = (float)poss[tid];
    }
    for (int j = tid; j < (TT + 1) * (TT + 1); j += 256)
        out[60 + (TT + 1) * (DEPTH + 2) + j] = (float)((&m[0][0])[j]);
}

// ---------------- launch ----------------
extern "C" void kernel_launch(void* const* d_in, const int* in_sizes, int n_in,
                              void* d_out, int out_size)
{
    const float* lh     = (const float*)d_in[0];
    const float* E      = (const float*)d_in[1];
    const float* W_fc   = (const float*)d_in[2];
    const float* W_head = (const float*)d_in[3];
    const int*   stok   = (const int*)d_in[4];
    float* out = (float*)d_out;

    const int HB = (VOCAB + 511) / 512;   // 63 col-blocks for head (guarded)
    const int FB = D_MODEL / 512;         // 8 col-blocks for fc

    // init stage
    hdup_init_kernel<<<16, 256>>>(lh);
    pipe_gemm<1, 0><<<dim3(HB, HSNUM), 128, SMEM_TOT>>>(W_head, D_MODEL, VOCAB, T_HEAD, HSNUM);
    head_topk_part<HSNUM><<<dim3(1, VSPLIT), 512>>>(1);
    init_merge_kernel<<<1, 128>>>();

    for (int i = 0; i < DEPTH; i++) {
        prep_fc_dup_kernel<<<80, 256>>>(E, lh, i);
        pipe_gemm<TK, 1><<<dim3(FB, FSNUM), 128, SMEM_TOT>>>(W_fc, KFC, D_MODEL, T_FC, FSNUM);
        fc_reduce_kernel<<<160, 128>>>();
        pipe_gemm<TK, 0><<<dim3(HB, HSNUM), 128, SMEM_TOT>>>(W_head, D_MODEL, VOCAB, T_HEAD, HSNUM);
        head_topk_part<HSNUM><<<dim3(TK, VSPLIT), 512>>>(TK);
        level_kernel<<<1, 128>>>(i);
    }
    final_kernel<<<1, 256>>>(stok, out);
}

// round 15
// speedup vs baseline: 1.0269x; 1.0269x over previous
#include <cuda_runtime.h>
#include <cstdint>
#include <cfloat>
#include <math.h>

#define D_MODEL 4096
#define VOCAB   32000
#define TK      10
#define DEPTH   5
#define TT      59
#define VSPLIT  16
#define KFC     (2*D_MODEL)

#define KTILE   8
#define NBUF    2
#define SMEM_W  (NBUF*KTILE*512*4)     // 32768 B
#define SMEM_H  (NBUF*KTILE*12*8)      // 1536 B (head gemm h staging)
#define SMEM_TOT (SMEM_W + SMEM_H)     // 34304 B

// fc gemm: W buffers + whole-range h tile gathered at start
#define FMAXT   12                     // max k-tiles per fc split
#define SMEM_HF (FMAXT*KTILE*12*8)     // 9216 B
#define SMEM_FC (SMEM_W + SMEM_HF)     // 41984 B -> 5 CTAs/SM

#define HSNUM   14       // head split: 63 x 14 = 882 CTAs (one wave @6/SM)
#define FSNUM   92       // fc split:    8 x 92 = 736 CTAs (one wave @5/SM)
#define T_HEAD  (D_MODEL / KTILE)      // 512 k-tiles
#define T_FC    (KFC / KTILE)          // 1024 k-tiles

typedef unsigned long long ull;

// ---------------- device scratch ----------------
__device__ __align__(16) float g_part[4718592];   // split-K partials
__device__ float  g_outh[TK][D_MODEL];            // fc output (tanh)
__device__ ull    g_hdupA[TK * D_MODEL];          // dup'd h for head gemm
__device__ float  g_scores_flat[512];
__device__ int    g_ss_flat[512];
__device__ int    g_parents_flat[64];
__device__ float  g_scores[TK];
__device__ int    g_input_ids[TK];
__device__ int    g_out_ids[TK];
__device__ int    g_cs_index[TK];
__device__ float  g_topk_p[TK][TK];
__device__ int    g_topk_i[TK][TK];
__device__ float  g_cand_v[TK][VSPLIT][TK];
__device__ int    g_cand_i[TK][VSPLIT][TK];
__device__ float  g_lse_m[TK][VSPLIT];
__device__ float  g_lse_s[TK][VSPLIT];

// ---------------- helpers ----------------
__device__ __forceinline__ void ffma2(ull &acc, ull a, ull b) {
    asm("fma.rn.f32x2 %0, %1, %2, %0;" : "+l"(acc) : "l"(a), "l"(b));
}

__device__ __forceinline__ ull dupf(float v) {
    unsigned u = __float_as_uint(v);
    return (ull)u | ((ull)u << 32);
}

__device__ __forceinline__ bool betterf(float av, int ai, float bv, int bi) {
    return (av > bv) || (av == bv && ai < bi);
}

__device__ __forceinline__ void cpa16(uint32_t s, const void* g) {
    asm volatile("cp.async.cg.shared.global [%0], [%1], 16;" :: "r"(s), "l"(g) : "memory");
}
__device__ __forceinline__ void cpa8(uint32_t s, const void* g) {
    asm volatile("cp.async.ca.shared.global [%0], [%1], 8;" :: "r"(s), "l"(g) : "memory");
}
#define CP_COMMIT() asm volatile("cp.async.commit_group;" ::: "memory")
#define CP_WAIT()   asm volatile("cp.async.wait_group %0;" :: "n"(NBUF - 1) : "memory")

// ---------------- inner-product body (shared by both gemms) ----------------
template<int ROWS>
__device__ __forceinline__ void tile_fma(const char* wrow, const char* hrow,
                                         ull* acc0, ull* acc1)
{
    #pragma unroll
    for (int kk = 0; kk < KTILE; kk++) {
        float4 wv = *reinterpret_cast<const float4*>(wrow + kk * 2048);
        ulonglong2 wp = *reinterpret_cast<ulonglong2*>(&wv);
        #pragma unroll
        for (int rp = 0; rp < ROWS / 2; rp++) {
            ulonglong2 h = *reinterpret_cast<const ulonglong2*>(hrow + kk * 96 + rp * 16);
            ffma2(acc0[2*rp],   wp.x, h.x);
            ffma2(acc1[2*rp],   wp.y, h.x);
            ffma2(acc0[2*rp+1], wp.x, h.y);
            ffma2(acc1[2*rp+1], wp.y, h.y);
        }
        if (ROWS & 1) {
            ull h = *reinterpret_cast<const ull*>(hrow + kk * 96 + (ROWS - 1) * 8);
            ffma2(acc0[ROWS-1], wp.x, h);
            ffma2(acc1[ROWS-1], wp.y, h);
        }
    }
}

// ---------------- head gemm: cp.async W + cp.async h from g_hdupA ----------------
template<int ROWS>
__global__ __launch_bounds__(128)
void pipe_gemm_head(const float* __restrict__ W, int K, int N, int T, int S)
{
    extern __shared__ char smem[];
    const int tid  = threadIdx.x;
    const int colb = blockIdx.x * 512;
    const int col  = colb + tid * 4;
    const bool vC  = col < N;
    const int ts   = (blockIdx.y * T) / S;
    const int te   = ((blockIdx.y + 1) * T) / S;

    const uint32_t wbase = (uint32_t)__cvta_generic_to_shared(smem);
    const uint32_t hbase = wbase + SMEM_W;

    ull acc0[ROWS], acc1[ROWS];
    #pragma unroll
    for (int r = 0; r < ROWS; r++) { acc0[r] = 0; acc1[r] = 0; }

    int gc = colb + tid * 4;
    gc = (gc <= N - 4) ? gc : (N - 4);

    auto stage = [&](int kt, int b) {
        const float* ws = W + (size_t)kt * KTILE * N;
        const uint32_t wd = wbase + (uint32_t)b * (KTILE * 512 * 4);
        #pragma unroll
        for (int u = 0; u < KTILE; u++)
            cpa16(wd + (uint32_t)(u * 2048 + tid * 16), ws + (size_t)u * N + gc);
        if (tid < ROWS * KTILE) {
            int r  = tid / KTILE;
            int kk = tid - r * KTILE;
            cpa8(hbase + (uint32_t)b * (KTILE * 12 * 8) + (uint32_t)(kk * 96 + r * 8),
                 g_hdupA + (size_t)r * K + (size_t)kt * KTILE + kk);
        }
    };

    #pragma unroll
    for (int s = 0; s < NBUF; s++) {
        if (ts + s < te) stage(ts + s, s);
        CP_COMMIT();
    }

    for (int i = ts; i < te; i++) {
        CP_WAIT();
        __syncthreads();
        const int b = (i - ts) & (NBUF - 1);
        tile_fma<ROWS>(smem + (size_t)b * (KTILE * 512 * 4) + tid * 16,
                       smem + SMEM_W + (size_t)b * (KTILE * 12 * 8), acc0, acc1);
        __syncthreads();
        if (i + NBUF < te) stage(i + NBUF, b);
        CP_COMMIT();
    }

    if (vC) {
        float* dst = g_part + (size_t)blockIdx.y * ROWS * N + col;
        #pragma unroll
        for (int r = 0; r < ROWS; r++) {
            ulonglong2 o; o.x = acc0[r]; o.y = acc1[r];
            *reinterpret_cast<ulonglong2*>(dst + (size_t)r * N) = o;
        }
    }
}

// ---------------- fc gemm: cp.async W + whole-range h gathered into smem ----------------
__global__ __launch_bounds__(128)
void pipe_gemm_fc(const float* __restrict__ W, const float* __restrict__ E,
                  const float* __restrict__ lh, int level)
{
    extern __shared__ char smem[];
    const int tid  = threadIdx.x;
    const int colb = blockIdx.x * 512;
    const int col  = colb + tid * 4;
    const int N    = D_MODEL;
    const int ts   = (blockIdx.y * T_FC) / FSNUM;
    const int te   = ((blockIdx.y + 1) * T_FC) / FSNUM;
    const int nk   = (te - ts) * KTILE;     // <= FMAXT*KTILE k's

    const uint32_t wbase = (uint32_t)__cvta_generic_to_shared(smem);
    char* htile = smem + SMEM_W;            // [nk][12] ull rows (96B stride)

    // one-time gather of this CTA's full h slice
    for (int x = tid; x < nk * TK; x += 128) {
        int kloc = x / TK, r = x - kloc * TK;
        int k = ts * KTILE + kloc;
        float v;
        if (k < D_MODEL)        v = E[(size_t)g_input_ids[r] * D_MODEL + k];
        else if (level == 0)    v = lh[k - D_MODEL];
        else                    v = g_outh[g_out_ids[r]][k - D_MODEL];
        *reinterpret_cast<ull*>(htile + kloc * 96 + r * 8) = dupf(v);
    }

    ull acc0[TK], acc1[TK];
    #pragma unroll
    for (int r = 0; r < TK; r++) { acc0[r] = 0; acc1[r] = 0; }

    auto stage = [&](int kt, int b) {
        const float* ws = W + (size_t)kt * KTILE * N;
        const uint32_t wd = wbase + (uint32_t)b * (KTILE * 512 * 4);
        #pragma unroll
        for (int u = 0; u < KTILE; u++)
            cpa16(wd + (uint32_t)(u * 2048 + tid * 16), ws + (size_t)u * N + colb + tid * 4);
    };

    #pragma unroll
    for (int s = 0; s < NBUF; s++) {
        if (ts + s < te) stage(ts + s, s);
        CP_COMMIT();
    }

    for (int i = ts; i < te; i++) {
        CP_WAIT();
        __syncthreads();   // also orders the initial h gather before first use
        const int b = (i - ts) & (NBUF - 1);
        tile_fma<TK>(smem + (size_t)b * (KTILE * 512 * 4) + tid * 16,
                     htile + (size_t)(i - ts) * (KTILE * 96), acc0, acc1);
        __syncthreads();
        if (i + NBUF < te) stage(i + NBUF, b);
        CP_COMMIT();
    }

    float* dst = g_part + (size_t)blockIdx.y * TK * N + col;
    #pragma unroll
    for (int r = 0; r < TK; r++) {
        ulonglong2 o; o.x = acc0[r]; o.y = acc1[r];
        *reinterpret_cast<ulonglong2*>(dst + (size_t)r * N) = o;
    }
}

// ---------------- per-slice partial-reduce + streaming LSE + top-10 ----------------
template<int NS>
__global__ __launch_bounds__(512)
void head_topk_part(int rows)
{
    __shared__ float sval[512 * 10];
    __shared__ int   sidx[512 * 10];
    __shared__ float sm[512];
    __shared__ float ssm[512];
    const int r   = blockIdx.x;
    const int s   = blockIdx.y;
    const int tid = threadIdx.x;
    const int q0  = s * (VOCAB / VSPLIT / 4);
    const int q1  = q0 + (VOCAB / VSPLIT / 4);

    float bv[10]; int bi[10];
    #pragma unroll
    for (int j = 0; j < 10; j++) { bv[j] = -FLT_MAX; bi[j] = 0x7fffffff; }
    float runm = -FLT_MAX, runs = 0.f;

    const float4* pp = reinterpret_cast<const float4*>(g_part);
    for (int q = q0 + tid; q < q1; q += 512) {
        float4 a = pp[((size_t)0 * rows + r) * (VOCAB / 4) + q];
        #pragma unroll 7
        for (int p = 1; p < NS; p++) {
            float4 t = pp[((size_t)p * rows + r) * (VOCAB / 4) + q];
            a.x += t.x; a.y += t.y; a.z += t.z; a.w += t.w;
        }
        int vbase = q * 4;
        float xs[4] = {a.x, a.y, a.z, a.w};
        #pragma unroll
        for (int e = 0; e < 4; e++) {
            float x = xs[e];
            int   v = vbase + e;
            float nm = fmaxf(runm, x);
            runs = runs * __expf(runm - nm) + __expf(x - nm);
            runm = nm;
            if (betterf(x, v, bv[9], bi[9])) {
                bv[9] = x; bi[9] = v;
                #pragma unroll
                for (int j = 9; j > 0; j--) {
                    if (betterf(bv[j], bi[j], bv[j-1], bi[j-1])) {
                        float tv = bv[j]; bv[j] = bv[j-1]; bv[j-1] = tv;
                        int   ti = bi[j]; bi[j] = bi[j-1]; bi[j-1] = ti;
                    }
                }
            }
        }
    }
    #pragma unroll
    for (int j = 0; j < 10; j++) { sval[tid*10+j] = bv[j]; sidx[tid*10+j] = bi[j]; }
    sm[tid] = runm; ssm[tid] = runs;
    __syncthreads();

    for (int n = 256; n >= 1; n >>= 1) {
        if (tid < n) {
            const float* pa = &sval[tid * 10];
            const int*   qa = &sidx[tid * 10];
            const float* pb = &sval[(tid + n) * 10];
            const int*   qb = &sidx[(tid + n) * 10];
            float ov[10]; int oi[10];
            int ia = 0, ib = 0;
            #pragma unroll
            for (int j = 0; j < 10; j++) {
                bool ta = betterf(pa[ia], qa[ia], pb[ib], qb[ib]);
                ov[j] = ta ? pa[ia] : pb[ib];
                oi[j] = ta ? qa[ia] : qb[ib];
                if (ta) ia++; else ib++;
            }
            #pragma unroll
            for (int j = 0; j < 10; j++) { sval[tid*10+j] = ov[j]; sidx[tid*10+j] = oi[j]; }
            float m1 = sm[tid], m2 = sm[tid + n];
            float mm = fmaxf(m1, m2);
            ssm[tid] = ssm[tid] * __expf(m1 - mm) + ssm[tid + n] * __expf(m2 - mm);
            sm[tid] = mm;
        }
        __syncthreads();
    }
    if (tid < 10) {
        g_cand_v[r][s][tid] = sval[tid];
        g_cand_i[r][s][tid] = sidx[tid];
        if (tid == 0) { g_lse_m[r][s] = sm[0]; g_lse_s[r][s] = ssm[0]; }
    }
}

// ---------------- smem-cached merge ----------------
__device__ __forceinline__ void merge_from_smem(
    int r, const float (*scv)[VSPLIT][TK], const int (*sci)[VSPLIT][TK],
    const float (*slm)[VSPLIT], const float (*sls)[VSPLIT])
{
    float mt = -FLT_MAX;
    #pragma unroll
    for (int s = 0; s < VSPLIT; s++) mt = fmaxf(mt, slm[r][s]);
    float st = 0.f;
    #pragma unroll
    for (int s = 0; s < VSPLIT; s++) st += sls[r][s] * __expf(slm[r][s] - mt);
    float lse = logf(st) + mt;

    int ptr[VSPLIT];
    #pragma unroll
    for (int s = 0; s < VSPLIT; s++) ptr[s] = 0;
    #pragma unroll
    for (int j = 0; j < TK; j++) {
        float bvv = -FLT_MAX; int bii = 0x7fffffff; int bs = 0;
        #pragma unroll
        for (int s = 0; s < VSPLIT; s++) {
            float cv = scv[r][s][ptr[s]];
            int   ci = sci[r][s][ptr[s]];
            if (betterf(cv, ci, bvv, bii)) { bvv = cv; bii = ci; bs = s; }
        }
        ptr[bs]++;
        g_topk_p[r][j] = bvv - lse;
        g_topk_i[r][j] = bii;
    }
}

__global__ __launch_bounds__(128)
void init_merge_kernel()
{
    __shared__ float scv[1][VSPLIT][TK];
    __shared__ int   sci[1][VSPLIT][TK];
    __shared__ float slm[1][VSPLIT];
    __shared__ float sls[1][VSPLIT];
    int tid = threadIdx.x;
    for (int x = tid; x < VSPLIT * TK; x += 128) {
        (&scv[0][0][0])[x] = (&g_cand_v[0][0][0])[x];
        (&sci[0][0][0])[x] = (&g_cand_i[0][0][0])[x];
    }
    if (tid < VSPLIT) { slm[0][tid] = g_lse_m[0][tid]; sls[0][tid] = g_lse_s[0][tid]; }
    __syncthreads();
    if (tid == 0) {
        merge_from_smem(0, scv, sci, slm, sls);
        #pragma unroll
        for (int j = 0; j < TK; j++) {
            float lp = g_topk_p[0][j];
            int   ix = g_topk_i[0][j];
            g_scores[j]      = lp;
            g_scores_flat[j] = lp;
            g_ss_flat[j]     = ix;
            g_input_ids[j]   = ix;
            g_cs_index[j]    = j;
        }
        g_parents_flat[0] = 0;
    }
}

// ---------------- fused merge + level bookkeeping ----------------
__global__ __launch_bounds__(128)
void level_kernel(int level)
{
    __shared__ float scv[TK][VSPLIT][TK];
    __shared__ int   sci[TK][VSPLIT][TK];
    __shared__ float slm[TK][VSPLIT];
    __shared__ float sls[TK][VSPLIT];
    __shared__ float cu[128];
    __shared__ float rv[128];
    __shared__ int   ri[128];
    int tid = threadIdx.x;

    for (int x = tid; x < TK * VSPLIT * TK; x += 128) {
        (&scv[0][0][0])[x] = (&g_cand_v[0][0][0])[x];
        (&sci[0][0][0])[x] = (&g_cand_i[0][0][0])[x];
    }
    for (int x = tid; x < TK * VSPLIT; x += 128) {
        (&slm[0][0])[x] = (&g_lse_m[0][0])[x];
        (&sls[0][0])[x] = (&g_lse_s[0][0])[x];
    }
    if (tid < TK) {
        int bias1 = (level > 0) ? TK : 0;
        int bias2 = (level > 1) ? (level - 1) : 0;
        int bias  = 1 + TK * TK * bias2 + bias1;
        g_parents_flat[1 + TK * level + tid] = g_cs_index[tid] + bias;
    }
    __syncthreads();
    if (tid < TK) merge_from_smem(tid, scv, sci, slm, sls);
    __syncthreads();
    float v = -FLT_MAX;
    if (tid < 100) {
        int r = tid / 10, c = tid - r * 10;
        v = g_topk_p[r][c] + g_scores[r];
        g_scores_flat[10 + 100 * level + tid] = v;
        g_ss_flat[10 + 100 * level + tid]     = g_topk_i[r][c];
    }
    cu[tid] = v;
    __syncthreads();
    for (int j = 0; j < TK; j++) {
        rv[tid] = cu[tid]; ri[tid] = tid;
        __syncthreads();
        #pragma unroll
        for (int n = 64; n >= 1; n >>= 1) {
            if (tid < n) {
                if (betterf(rv[tid + n], ri[tid + n], rv[tid], ri[tid])) {
                    rv[tid] = rv[tid + n]; ri[tid] = ri[tid + n];
                }
            }
            __syncthreads();
        }
        if (tid == 0) {
            int bx = ri[0];
            g_cs_index[j]  = bx;
            g_scores[j]    = rv[0];
            g_out_ids[j]   = bx / 10;
            g_input_ids[j] = g_topk_i[bx / 10][bx % 10];
            cu[bx] = -FLT_MAX;
        }
        __syncthreads();
    }
}

// ---------------- hdup init ----------------
__global__ void hdup_init_kernel(const float* __restrict__ lh)
{
    int j = blockIdx.x * 256 + threadIdx.x;
    if (j < D_MODEL) g_hdupA[j] = dupf(lh[j]);
}

// ---------------- fc reduce: sum FSNUM partials, tanh, write outh + hdupA ----------------
__global__ __launch_bounds__(128)
void fc_reduce_kernel()
{
    int q = blockIdx.x * 128 + threadIdx.x;     // 160 blocks * 128 = 20480 float2s
    const float2* pp = reinterpret_cast<const float2*>(g_part);
    float ax = 0.f, ay = 0.f;
    #pragma unroll 8
    for (int p = 0; p < FSNUM; p++) {
        float2 t = pp[(size_t)p * (TK * D_MODEL / 2) + q];
        ax += t.x; ay += t.y;
    }
    float t0 = tanhf(ax), t1 = tanhf(ay);
    reinterpret_cast<float2*>(&g_outh[0][0])[q] = make_float2(t0, t1);
    int r = q / (D_MODEL / 2);
    int c = (q - r * (D_MODEL / 2)) * 2;
    g_hdupA[(size_t)r * D_MODEL + c]     = dupf(t0);
    g_hdupA[(size_t)r * D_MODEL + c + 1] = dupf(t1);
}

// ---------------- final tree assembly ----------------
__global__ __launch_bounds__(256)
void final_kernel(const int* __restrict__ sample_token, float* __restrict__ out)
{
    __shared__ float sv[512];
    __shared__ float rv[256];
    __shared__ int   ri[256];
    __shared__ int   tsi_u[TT];
    __shared__ int   tsi[TT];
    __shared__ int   pp[TT + 1];
    __shared__ unsigned char noleaf[TT + 1];
    __shared__ unsigned char m[TT + 1][TT + 1];
    __shared__ int   poss[TT + 1];
    const int tid = threadIdx.x;

    for (int j = tid; j < 512; j += 256)
        sv[j] = (j < 510) ? g_scores_flat[j] : -FLT_MAX;
    __syncthreads();

    for (int round = 0; round < TT; round++) {
        float a = sv[tid], b = sv[tid + 256];
        float mv; int mi;
        if (betterf(a, tid, b, tid + 256)) { mv = a; mi = tid; } else { mv = b; mi = tid + 256; }
        rv[tid] = mv; ri[tid] = mi;
        __syncthreads();
        for (int n = 128; n >= 1; n >>= 1) {
            if (tid < n) {
                if (betterf(rv[tid + n], ri[tid + n], rv[tid], ri[tid])) {
                    rv[tid] = rv[tid + n]; ri[tid] = ri[tid + n];
                }
            }
            __syncthreads();
        }
        if (tid == 0) { tsi_u[round] = ri[0]; sv[ri[0]] = -FLT_MAX; }
        __syncthreads();
    }

    if (tid < TT) {
        int v = tsi_u[tid];
        int rank = 0;
        for (int j = 0; j < TT; j++) rank += (tsi_u[j] < v);
        tsi[rank] = v;
    }
    __syncthreads();

    if (tid < TT) {
        int t  = tsi[tid];
        int dp = g_parents_flat[t / TK];
        int tgt = dp - 1;
        int lb = 0;
        for (int j = 0; j < TT; j++) lb += (tsi[j] < tgt);
        int mi = ((dp == 0) ? -1 : lb) + 1;
        pp[tid + 1] = mi;
    }
    if (tid == 0) pp[0] = 0;
    if (tid <= TT) noleaf[tid] = 0;
    for (int j = tid; j < (TT + 1) * (TT + 1); j += 256)
        (&m[0][0])[j] = 0;
    __syncthreads();
    if (tid < TT) noleaf[pp[tid + 1]] = 1;
    __syncthreads();

    int a[DEPTH + 2];
    int pos = 0;
    if (tid <= TT) {
        a[0] = tid;
        #pragma unroll
        for (int jj = 1; jj < DEPTH + 2; jj++) a[jj] = pp[a[jj - 1]];
        #pragma unroll
        for (int jj = 0; jj < DEPTH + 2; jj++) m[tid][a[jj]] = 1;
        m[tid][0] = 1;
    }
    __syncthreads();
    if (tid <= TT) {
        int s = 0;
        for (int c = 0; c <= TT; c++) s += m[tid][c];
        pos = s - 1;
        poss[tid] = pos;
    }
    __syncthreads();

    if (tid == 0) out[0] = (float)sample_token[0];
    if (tid < TT) out[1 + tid] = (float)g_ss_flat[tsi[tid]];
    if (tid <= TT) {
        #pragma unroll
        for (int c = 0; c < DEPTH + 2; c++) {
            int kk  = pos - c;
            int idx = kk < 0 ? 0 : (kk > DEPTH + 1 ? DEPTH + 1 : kk);
            int ch  = (kk >= 0) ? a[idx] : -1;
            if (noleaf[tid]) ch = -1;
            out[60 + tid * (DEPTH + 2) + c] = (float)ch;
        }
        out[60 + (TT + 1) * (DEPTH + 2) + (TT + 1) * (TT + 1) + tid] = (float)poss[tid];
    }
    for (int j = tid; j < (TT + 1) * (TT + 1); j += 256)
        out[60 + (TT + 1) * (DEPTH + 2) + j] = (float)((&m[0][0])[j]);
}

// ---------------- launch ----------------
extern "C" void kernel_launch(void* const* d_in, const int* in_sizes, int n_in,
                              void* d_out, int out_size)
{
    const float* lh     = (const float*)d_in[0];
    const float* E      = (const float*)d_in[1];
    const float* W_fc   = (const float*)d_in[2];
    const float* W_head = (const float*)d_in[3];
    const int*   stok   = (const int*)d_in[4];
    float* out = (float*)d_out;

    const int HB = (VOCAB + 511) / 512;   // 63 col-blocks for head (guarded)
    const int FB = D_MODEL / 512;         // 8 col-blocks for fc

    // init stage
    hdup_init_kernel<<<16, 256>>>(lh);
    pipe_gemm_head<1><<<dim3(HB, HSNUM), 128, SMEM_TOT>>>(W_head, D_MODEL, VOCAB, T_HEAD, HSNUM);
    head_topk_part<HSNUM><<<dim3(1, VSPLIT), 512>>>(1);
    init_merge_kernel<<<1, 128>>>();

    for (int i = 0; i < DEPTH; i++) {
        pipe_gemm_fc<<<dim3(FB, FSNUM), 128, SMEM_FC>>>(W_fc, E, lh, i);
        fc_reduce_kernel<<<160, 128>>>();
        pipe_gemm_head<TK><<<dim3(HB, HSNUM), 128, SMEM_TOT>>>(W_head, D_MODEL, VOCAB, T_HEAD, HSNUM);
        head_topk_part<HSNUM><<<dim3(TK, VSPLIT), 512>>>(TK);
        level_kernel<<<1, 128>>>(i);
    }
    final_kernel<<<1, 256>>>(stok, out);
}